// round 6
// baseline (speedup 1.0000x reference)
#include <cuda_runtime.h>
#include <cstdint>

// Problem constants (scratch sized for this problem; clamped at launch).
#define NN 50000
#define EE 800000

// Scratch accumulators: num[n*64+cf] = sum over edges->n of m*exp(z),
//                       den[n*64+cf] = sum over edges->n of exp(z).
// Zero-initialized at module load; node kernel re-zeroes after consuming,
// so every kernel_launch execution sees zeroed accumulators.
__device__ __align__(16) float g_num[(size_t)NN * 64];
__device__ __align__(16) float g_den[(size_t)NN * 64];

__device__ __forceinline__ void red_add_v4(float* addr, float a, float b, float c, float d) {
    asm volatile("red.global.add.v4.f32 [%0], {%1, %2, %3, %4};"
                 :: "l"(addr), "f"(a), "f"(b), "f"(c), "f"(d) : "memory");
}

// ---------------------------------------------------------------------------
// Kernel 1: edge pass. 16 threads per edge; thread handles 4 consecutive
// stacked features cf = l*4 .. l*4+3 (component c = l>>2, float4 v = l&3).
// Softmax without the max pass (z = beta*msg is small; exp is fp32-safe,
// and num/den is shift-invariant). One v4 RED per accumulator per thread.
// ---------------------------------------------------------------------------
__global__ __launch_bounds__(256)
void qmp_edge_kernel(const float* __restrict__ q,
                     const float* __restrict__ edge_attr,
                     const int*   __restrict__ edge_index,
                     const float* __restrict__ beta,
                     int N, int E)
{
    float bta = __ldg(beta);

    long long tid = (long long)blockIdx.x * blockDim.x + threadIdx.x;
    int e = (int)(tid >> 4);
    if (e >= E) return;
    int l = (int)(tid & 15);  // 0..15 -> stacked features l*4..l*4+3
    int c = l >> 2;           // quaternion component
    int v = l & 3;            // float4 index within component

    int src = edge_index[e];
    int dst = edge_index[E + e];

    const float4 qv = *reinterpret_cast<const float4*>(
        q + ((size_t)c * N + src) * 16 + v * 4);
    const float4 ev = *reinterpret_cast<const float4*>(
        edge_attr + ((size_t)c * E + e) * 16 + v * 4);

    float mx = qv.x + ev.x;
    float my = qv.y + ev.y;
    float mz = qv.z + ev.z;
    float mw = qv.w + ev.w;

    float ex = __expf(mx * bta);
    float ey = __expf(my * bta);
    float ez = __expf(mz * bta);
    float ew = __expf(mw * bta);

    size_t base = (size_t)dst * 64 + (size_t)l * 4;
    red_add_v4(g_den + base, ex, ey, ez, ew);
    red_add_v4(g_num + base, mx * ex, my * ey, mz * ez, mw * ew);
}

// ---------------------------------------------------------------------------
// Kernel 2: node pass (cooperative, no per-thread spill).
// Block = 128 threads handles 128 nodes. Thread: co = tid&3 (output
// quaternion component), quad = tid>>2; it owns 4 nodes (quad*4+t) and
// computes their 16 output features of component co.
// x and h are staged in shared memory as [cf][node_local].
// Also re-zeroes the consumed num/den entries (replaces the zero kernel).
// ---------------------------------------------------------------------------
#define SXS 132            // node-dim stride (conflict-free reads: quads hit distinct banks)
#define WST 264            // per-component weight stride

__global__ __launch_bounds__(128)
void qmp_node_kernel(const float* __restrict__ q,
                     const float* __restrict__ W1, const float* __restrict__ b1,
                     const float* __restrict__ W2, const float* __restrict__ b2,
                     float* __restrict__ out, int N)
{
    __shared__ float sW1[4 * WST];
    __shared__ float sW2[4 * WST];
    __shared__ float sb1[64], sb2[64], ssg[16];
    __shared__ float sx[64][SXS];

    const int tid = threadIdx.x;

    // Load weights/biases/sign table.
    for (int i = tid; i < 1024; i += 128) {
        int c = i >> 8, r = i & 255;
        sW1[c * WST + r] = W1[i];
        sW2[c * WST + r] = W2[i];
    }
    if (tid < 64) { sb1[tid] = b1[tid]; sb2[tid] = b2[tid]; }
    if (tid < 16) {
        int co = tid >> 2, cx = tid & 3;
        // Hamilton sign: +1 for cx==0; row co==0 negative for cx>0;
        // for co>0,cx>0 negative iff cx == ((co+1)%3)+1.
        float s = 1.f;
        if (cx != 0) {
            if (co == 0) s = -1.f;
            else if (cx == ((co + 1) % 3) + 1) s = -1.f;
        }
        ssg[tid] = s;
    }

    const int co   = tid & 3;
    const int quad = tid >> 2;
    const int nb   = blockIdx.x * 128;      // first node of this block
    const int nl0  = quad * 4;              // first local node of this thread

    const float4 zero4 = make_float4(0.f, 0.f, 0.f, 0.f);

    // Phase A: x[cf][node] = q + num/den; then zero num/den for next run.
#pragma unroll
    for (int t = 0; t < 4; t++) {
        int n = nb + nl0 + t;
        if (n >= N) break;
#pragma unroll
        for (int v = 0; v < 4; v++) {
            float4 qv = *reinterpret_cast<const float4*>(
                q + ((size_t)co * N + n) * 16 + v * 4);
            float4* nmp = reinterpret_cast<float4*>(
                g_num + (size_t)n * 64 + co * 16 + v * 4);
            float4* dnp = reinterpret_cast<float4*>(
                g_den + (size_t)n * 64 + co * 16 + v * 4);
            float4 nm = *nmp;
            float4 dn = *dnp;
            *nmp = zero4;
            *dnp = zero4;
            int cf = co * 16 + v * 4;
            sx[cf + 0][nl0 + t] = qv.x + (dn.x > 0.f ? nm.x / dn.x : 0.f);
            sx[cf + 1][nl0 + t] = qv.y + (dn.y > 0.f ? nm.y / dn.y : 0.f);
            sx[cf + 2][nl0 + t] = qv.z + (dn.z > 0.f ? nm.z / dn.z : 0.f);
            sx[cf + 3][nl0 + t] = qv.w + (dn.w > 0.f ? nm.w / dn.w : 0.f);
        }
    }
    __syncthreads();

    float acc[4][16];

    // ---- Layer 1: h = relu(b1 + Hamilton(x, W1)) ----
    {
#pragma unroll
        for (int t = 0; t < 4; t++)
#pragma unroll
            for (int f = 0; f < 16; f++) acc[t][f] = sb1[co * 16 + f];

#pragma unroll
        for (int cx = 0; cx < 4; cx++) {
            const float* W = &sW1[(co ^ cx) * WST];
            const float s = ssg[co * 4 + cx];
#pragma unroll
            for (int fi = 0; fi < 16; fi++) {
                float xv0 = s * sx[cx * 16 + fi][nl0 + 0];
                float xv1 = s * sx[cx * 16 + fi][nl0 + 1];
                float xv2 = s * sx[cx * 16 + fi][nl0 + 2];
                float xv3 = s * sx[cx * 16 + fi][nl0 + 3];
#pragma unroll
                for (int v = 0; v < 4; v++) {
                    float4 w = *reinterpret_cast<const float4*>(W + fi * 16 + v * 4);
                    acc[0][v*4+0] = fmaf(xv0, w.x, acc[0][v*4+0]);
                    acc[0][v*4+1] = fmaf(xv0, w.y, acc[0][v*4+1]);
                    acc[0][v*4+2] = fmaf(xv0, w.z, acc[0][v*4+2]);
                    acc[0][v*4+3] = fmaf(xv0, w.w, acc[0][v*4+3]);
                    acc[1][v*4+0] = fmaf(xv1, w.x, acc[1][v*4+0]);
                    acc[1][v*4+1] = fmaf(xv1, w.y, acc[1][v*4+1]);
                    acc[1][v*4+2] = fmaf(xv1, w.z, acc[1][v*4+2]);
                    acc[1][v*4+3] = fmaf(xv1, w.w, acc[1][v*4+3]);
                    acc[2][v*4+0] = fmaf(xv2, w.x, acc[2][v*4+0]);
                    acc[2][v*4+1] = fmaf(xv2, w.y, acc[2][v*4+1]);
                    acc[2][v*4+2] = fmaf(xv2, w.z, acc[2][v*4+2]);
                    acc[2][v*4+3] = fmaf(xv2, w.w, acc[2][v*4+3]);
                    acc[3][v*4+0] = fmaf(xv3, w.x, acc[3][v*4+0]);
                    acc[3][v*4+1] = fmaf(xv3, w.y, acc[3][v*4+1]);
                    acc[3][v*4+2] = fmaf(xv3, w.z, acc[3][v*4+2]);
                    acc[3][v*4+3] = fmaf(xv3, w.w, acc[3][v*4+3]);
                }
            }
        }
    }
    __syncthreads();   // all x reads complete before h overwrites sx

    // relu + write h back to sx
#pragma unroll
    for (int t = 0; t < 4; t++)
#pragma unroll
        for (int f = 0; f < 16; f++)
            sx[co * 16 + f][nl0 + t] = fmaxf(acc[t][f], 0.f);
    __syncthreads();

    // ---- Layer 2: y = b2 + Hamilton(h, W2) ----
    {
#pragma unroll
        for (int t = 0; t < 4; t++)
#pragma unroll
            for (int f = 0; f < 16; f++) acc[t][f] = sb2[co * 16 + f];

#pragma unroll
        for (int cx = 0; cx < 4; cx++) {
            const float* W = &sW2[(co ^ cx) * WST];
            const float s = ssg[co * 4 + cx];
#pragma unroll
            for (int fi = 0; fi < 16; fi++) {
                float xv0 = s * sx[cx * 16 + fi][nl0 + 0];
                float xv1 = s * sx[cx * 16 + fi][nl0 + 1];
                float xv2 = s * sx[cx * 16 + fi][nl0 + 2];
                float xv3 = s * sx[cx * 16 + fi][nl0 + 3];
#pragma unroll
                for (int v = 0; v < 4; v++) {
                    float4 w = *reinterpret_cast<const float4*>(W + fi * 16 + v * 4);
                    acc[0][v*4+0] = fmaf(xv0, w.x, acc[0][v*4+0]);
                    acc[0][v*4+1] = fmaf(xv0, w.y, acc[0][v*4+1]);
                    acc[0][v*4+2] = fmaf(xv0, w.z, acc[0][v*4+2]);
                    acc[0][v*4+3] = fmaf(xv0, w.w, acc[0][v*4+3]);
                    acc[1][v*4+0] = fmaf(xv1, w.x, acc[1][v*4+0]);
                    acc[1][v*4+1] = fmaf(xv1, w.y, acc[1][v*4+1]);
                    acc[1][v*4+2] = fmaf(xv1, w.z, acc[1][v*4+2]);
                    acc[1][v*4+3] = fmaf(xv1, w.w, acc[1][v*4+3]);
                    acc[2][v*4+0] = fmaf(xv2, w.x, acc[2][v*4+0]);
                    acc[2][v*4+1] = fmaf(xv2, w.y, acc[2][v*4+1]);
                    acc[2][v*4+2] = fmaf(xv2, w.z, acc[2][v*4+2]);
                    acc[2][v*4+3] = fmaf(xv2, w.w, acc[2][v*4+3]);
                    acc[3][v*4+0] = fmaf(xv3, w.x, acc[3][v*4+0]);
                    acc[3][v*4+1] = fmaf(xv3, w.y, acc[3][v*4+1]);
                    acc[3][v*4+2] = fmaf(xv3, w.z, acc[3][v*4+2]);
                    acc[3][v*4+3] = fmaf(xv3, w.w, acc[3][v*4+3]);
                }
            }
        }
    }

    // Store y to out[co][n][f] (float4).
#pragma unroll
    for (int t = 0; t < 4; t++) {
        int n = nb + nl0 + t;
        if (n >= N) break;
        float* op = out + ((size_t)co * N + n) * 16;
#pragma unroll
        for (int v = 0; v < 4; v++) {
            float4 o = make_float4(acc[t][v*4+0], acc[t][v*4+1],
                                   acc[t][v*4+2], acc[t][v*4+3]);
            *reinterpret_cast<float4*>(op + v * 4) = o;
        }
    }
}

// ---------------------------------------------------------------------------
extern "C" void kernel_launch(void* const* d_in, const int* in_sizes, int n_in,
                              void* d_out, int out_size)
{
    const float* q    = (const float*)d_in[0];
    const float* ea   = (const float*)d_in[1];
    const int*   ei   = (const int*)  d_in[2];
    const float* W1   = (const float*)d_in[3];
    const float* b1   = (const float*)d_in[4];
    const float* W2   = (const float*)d_in[5];
    const float* b2   = (const float*)d_in[6];
    const float* beta = (const float*)d_in[7];
    float* out = (float*)d_out;

    int N = in_sizes[0] / 64;   // 4*F = 64 floats per node
    int E = in_sizes[1] / 64;   // 64 floats per edge
    if (N > NN) N = NN;         // scratch bound (sized to this problem)
    if (E > EE) E = EE;

    // 1) edge pass: 16 threads/edge (accumulators already zero: module-load
    //    init on the first run, node-pass re-zero on every subsequent run)
    long long tot = (long long)E * 16;
    int eb = (int)((tot + 255) / 256);
    qmp_edge_kernel<<<eb, 256>>>(q, ea, ei, beta, N, E);

    // 2) node pass: 128 nodes per 128-thread block (also re-zeroes scratch)
    qmp_node_kernel<<<(N + 127) / 128, 128>>>(q, W1, b1, W2, b2, out, N);
}

// round 8
// speedup vs baseline: 1.2143x; 1.2143x over previous
#include <cuda_runtime.h>
#include <cstdint>

// Problem constants (scratch sized for this problem; clamped at launch).
#define NN 50000
#define EE 800000

// Scratch accumulators: num[n*64+cf] = sum over edges->n of m*exp(z),
//                       den[n*64+cf] = sum over edges->n of exp(z).
// Zero-initialized at module load; node kernel re-zeroes after consuming,
// so every kernel_launch execution sees zeroed accumulators.
__device__ __align__(16) float g_num[(size_t)NN * 64];
__device__ __align__(16) float g_den[(size_t)NN * 64];

__device__ __forceinline__ void red_add_v4(float* addr, float a, float b, float c, float d) {
    asm volatile("red.global.add.v4.f32 [%0], {%1, %2, %3, %4};"
                 :: "l"(addr), "f"(a), "f"(b), "f"(c), "f"(d) : "memory");
}

// ---------------------------------------------------------------------------
// Kernel 1: edge pass. 16 threads per edge; thread handles 4 consecutive
// stacked features cf = l*4 .. l*4+3 (component c = l>>2, float4 v = l&3).
// Softmax without the max pass (z = beta*msg is small; exp is fp32-safe,
// and num/den is shift-invariant). One v4 RED per accumulator per thread.
// ---------------------------------------------------------------------------
__global__ __launch_bounds__(256)
void qmp_edge_kernel(const float* __restrict__ q,
                     const float* __restrict__ edge_attr,
                     const int*   __restrict__ edge_index,
                     const float* __restrict__ beta,
                     int N, int E)
{
    float bta = __ldg(beta);

    long long tid = (long long)blockIdx.x * blockDim.x + threadIdx.x;
    int e = (int)(tid >> 4);
    if (e >= E) return;
    int l = (int)(tid & 15);  // 0..15 -> stacked features l*4..l*4+3
    int c = l >> 2;           // quaternion component
    int v = l & 3;            // float4 index within component

    int src = edge_index[e];
    int dst = edge_index[E + e];

    const float4 qv = *reinterpret_cast<const float4*>(
        q + ((size_t)c * N + src) * 16 + v * 4);
    const float4 ev = *reinterpret_cast<const float4*>(
        edge_attr + ((size_t)c * E + e) * 16 + v * 4);

    float mx = qv.x + ev.x;
    float my = qv.y + ev.y;
    float mz = qv.z + ev.z;
    float mw = qv.w + ev.w;

    float ex = __expf(mx * bta);
    float ey = __expf(my * bta);
    float ez = __expf(mz * bta);
    float ew = __expf(mw * bta);

    size_t base = (size_t)dst * 64 + (size_t)l * 4;
    red_add_v4(g_den + base, ex, ey, ez, ew);
    red_add_v4(g_num + base, mx * ex, my * ey, mz * ez, mw * ew);
}

// ---------------------------------------------------------------------------
// Kernel 2: node pass, occupancy-oriented.
// Block = 256 threads handles 64 nodes. Thread = (node_l = tid>>2, co = tid&3):
// computes the 16 output features of component co for ONE node.
// x and h staged in shared sx[node][k] (k = stacked feature 0..63).
// Also re-zeroes the consumed num/den entries (replaces a zero kernel).
// ---------------------------------------------------------------------------
#define SXP 68             // k-stride per node (node address step = 4 banks)
#define WST 264            // per-component weight stride (bank-group step = 8)

__global__ __launch_bounds__(256)
void qmp_node_kernel(const float* __restrict__ q,
                     const float* __restrict__ W1, const float* __restrict__ b1,
                     const float* __restrict__ W2, const float* __restrict__ b2,
                     float* __restrict__ out, int N)
{
    __shared__ __align__(16) float sW1[4 * WST];
    __shared__ __align__(16) float sW2[4 * WST];
    __shared__ __align__(16) float sb1[64];
    __shared__ __align__(16) float sb2[64];
    __shared__ float ssg[16];
    __shared__ float sx[64 * SXP];

    const int tid = threadIdx.x;

    // Load weights/biases/sign table.
    for (int i = tid; i < 1024; i += 256) {
        int c = i >> 8, r = i & 255;
        sW1[c * WST + r] = W1[i];
        sW2[c * WST + r] = W2[i];
    }
    if (tid < 64) { sb1[tid] = b1[tid]; sb2[tid] = b2[tid]; }
    if (tid < 16) {
        int co = tid >> 2, cx = tid & 3;
        // Hamilton sign: +1 for cx==0; row co==0 negative for cx>0;
        // for co>0,cx>0 negative iff cx == ((co+1)%3)+1.
        float s = 1.f;
        if (cx != 0) {
            if (co == 0) s = -1.f;
            else if (cx == ((co + 1) % 3) + 1) s = -1.f;
        }
        ssg[tid] = s;
    }

    const int co     = tid & 3;
    const int node_l = tid >> 2;            // 0..63
    const int n      = blockIdx.x * 64 + node_l;
    float* sxn = sx + node_l * SXP;         // this node's k-row

    const float4 zero4 = make_float4(0.f, 0.f, 0.f, 0.f);

    // Phase A: x[k] = q + num/den for k-section co*16..co*16+15;
    // then zero num/den for the next run.
    if (n < N) {
#pragma unroll
        for (int v = 0; v < 4; v++) {
            float4 qv = *reinterpret_cast<const float4*>(
                q + ((size_t)co * N + n) * 16 + v * 4);
            float4* nmp = reinterpret_cast<float4*>(
                g_num + (size_t)n * 64 + co * 16 + v * 4);
            float4* dnp = reinterpret_cast<float4*>(
                g_den + (size_t)n * 64 + co * 16 + v * 4);
            float4 nm = *nmp;
            float4 dn = *dnp;
            *nmp = zero4;
            *dnp = zero4;
            int k = co * 16 + v * 4;
            sxn[k + 0] = qv.x + (dn.x > 0.f ? nm.x / dn.x : 0.f);
            sxn[k + 1] = qv.y + (dn.y > 0.f ? nm.y / dn.y : 0.f);
            sxn[k + 2] = qv.z + (dn.z > 0.f ? nm.z / dn.z : 0.f);
            sxn[k + 3] = qv.w + (dn.w > 0.f ? nm.w / dn.w : 0.f);
        }
    } else {
#pragma unroll
        for (int v = 0; v < 4; v++) {
            int k = co * 16 + v * 4;
            sxn[k + 0] = 0.f; sxn[k + 1] = 0.f;
            sxn[k + 2] = 0.f; sxn[k + 3] = 0.f;
        }
    }
    __syncthreads();

    float acc[16];

    // ---- Layer 1: h[co][:] = b1 + sum_cx sg * x[cx] @ W1[co^cx] ----
#pragma unroll
    for (int v = 0; v < 4; v++) {
        float4 b = *reinterpret_cast<const float4*>(sb1 + co * 16 + v * 4);
        acc[v*4+0] = b.x; acc[v*4+1] = b.y; acc[v*4+2] = b.z; acc[v*4+3] = b.w;
    }

    for (int cx = 0; cx < 4; cx++) {
        const float* W = &sW1[(co ^ cx) * WST];
        const float s = ssg[co * 4 + cx];
        const float* xp = sxn + cx * 16;
#pragma unroll
        for (int fi = 0; fi < 16; fi++) {
            float xv = s * xp[fi];
#pragma unroll
            for (int v = 0; v < 4; v++) {
                float4 w = *reinterpret_cast<const float4*>(W + fi * 16 + v * 4);
                acc[v*4+0] = fmaf(xv, w.x, acc[v*4+0]);
                acc[v*4+1] = fmaf(xv, w.y, acc[v*4+1]);
                acc[v*4+2] = fmaf(xv, w.z, acc[v*4+2]);
                acc[v*4+3] = fmaf(xv, w.w, acc[v*4+3]);
            }
        }
    }
    __syncthreads();   // all x reads done before h overwrites sx

    // relu + write h back to this thread's k-section
#pragma unroll
    for (int f = 0; f < 16; f++)
        sxn[co * 16 + f] = fmaxf(acc[f], 0.f);
    __syncthreads();

    // ---- Layer 2: y[co][:] = b2 + sum_cx sg * h[cx] @ W2[co^cx] ----
#pragma unroll
    for (int v = 0; v < 4; v++) {
        float4 b = *reinterpret_cast<const float4*>(sb2 + co * 16 + v * 4);
        acc[v*4+0] = b.x; acc[v*4+1] = b.y; acc[v*4+2] = b.z; acc[v*4+3] = b.w;
    }

    for (int cx = 0; cx < 4; cx++) {
        const float* W = &sW2[(co ^ cx) * WST];
        const float s = ssg[co * 4 + cx];
        const float* xp = sxn + cx * 16;
#pragma unroll
        for (int fi = 0; fi < 16; fi++) {
            float xv = s * xp[fi];
#pragma unroll
            for (int v = 0; v < 4; v++) {
                float4 w = *reinterpret_cast<const float4*>(W + fi * 16 + v * 4);
                acc[v*4+0] = fmaf(xv, w.x, acc[v*4+0]);
                acc[v*4+1] = fmaf(xv, w.y, acc[v*4+1]);
                acc[v*4+2] = fmaf(xv, w.z, acc[v*4+2]);
                acc[v*4+3] = fmaf(xv, w.w, acc[v*4+3]);
            }
        }
    }

    // Store y to out[co][n][0..15] (float4).
    if (n < N) {
        float* op = out + ((size_t)co * N + n) * 16;
#pragma unroll
        for (int v = 0; v < 4; v++) {
            float4 o = make_float4(acc[v*4+0], acc[v*4+1], acc[v*4+2], acc[v*4+3]);
            *reinterpret_cast<float4*>(op + v * 4) = o;
        }
    }
}

// ---------------------------------------------------------------------------
extern "C" void kernel_launch(void* const* d_in, const int* in_sizes, int n_in,
                              void* d_out, int out_size)
{
    const float* q    = (const float*)d_in[0];
    const float* ea   = (const float*)d_in[1];
    const int*   ei   = (const int*)  d_in[2];
    const float* W1   = (const float*)d_in[3];
    const float* b1   = (const float*)d_in[4];
    const float* W2   = (const float*)d_in[5];
    const float* b2   = (const float*)d_in[6];
    const float* beta = (const float*)d_in[7];
    float* out = (float*)d_out;

    int N = in_sizes[0] / 64;   // 4*F = 64 floats per node
    int E = in_sizes[1] / 64;   // 64 floats per edge
    if (N > NN) N = NN;         // scratch bound (sized to this problem)
    if (E > EE) E = EE;

    // 1) edge pass: 16 threads/edge (accumulators already zero: module-load
    //    init on the first run, node-pass re-zero on every subsequent run)
    long long tot = (long long)E * 16;
    int eb = (int)((tot + 255) / 256);
    qmp_edge_kernel<<<eb, 256>>>(q, ea, ei, beta, N, E);

    // 2) node pass: 64 nodes per 256-thread block (also re-zeroes scratch)
    qmp_node_kernel<<<(N + 63) / 64, 256>>>(q, W1, b1, W2, b2, out, N);
}